// round 9
// baseline (speedup 1.0000x reference)
#include <cuda_runtime.h>
#include <math.h>

// ----------------------------------------------------------------------------
// QuantumBranch, two-kernel split + PDL (round 9).
// expz0(t) = degree-12 trig polynomial in (pi*t), exactly.
//   K1 precompute (1 block): PARALLELIZED critical path --
//     lanes precompute the 27 theta sincos pairs and the 25 DFT twiddles in
//     parallel (smem), so the serial chain is just the gate math + 6 feature
//     sincos (~1.2k cycles, was ~6k).  Builds a 257-entry CENTERED cubic
//     table (float4 power basis, u in [-0.5,0.5]) -> __device__ global.
//   K2 eval (1024 blocks, one wave, PDL): stages 8 inputs/thread into smem
//     BEFORE cudaGridDependencySynchronize() (overlaps K1), then copies the
//     4.1 KB table and interpolates with the 2^23 magic index (no CVTs).
// Cubic error ~1.2e-6 at h=1/256  << 1e-3 tolerance.
// ----------------------------------------------------------------------------

#define NSAMP 25
#define NHARM 12
#define TBL   256
#define THREADS 256
#define ELEMS_PER_BLOCK (THREADS * 8)
#define PI_F  3.14159265358979323846f
#define TWO_PI_F 6.28318530717958647692f
#define MAGIC 8388608.0f   // 2^23

__device__ float4 g_table[TBL + 1];

struct cf { float re, im; };

__device__ __forceinline__ void gate1q(cf* s, int wire,
    float u00r, float u00i, float u01r, float u01i,
    float u10r, float u10i, float u11r, float u11i)
{
    const int str = 4 >> wire;
    #pragma unroll
    for (int k = 0; k < 8; k++) {
        if (k & str) continue;
        cf a = s[k], b = s[k + str];
        s[k].re       = u00r*a.re - u00i*a.im + u01r*b.re - u01i*b.im;
        s[k].im       = u00r*a.im + u00i*a.re + u01r*b.im + u01i*b.re;
        s[k + str].re = u10r*a.re - u10i*a.im + u11r*b.re - u11i*b.im;
        s[k + str].im = u10r*a.im + u10i*a.re + u11r*b.im + u11i*b.re;
    }
}

__device__ __forceinline__ void cnot(cf* s, int ctrl, int tgt)
{
    const int sc = 4 >> ctrl, st = 4 >> tgt;
    #pragma unroll
    for (int k = 0; k < 8; k++) {
        if (!(k & sc) || (k & st)) continue;
        cf tmp = s[k]; s[k] = s[k + st]; s[k + st] = tmp;
    }
}

// Ansatz layer using PRE-COMPUTED theta sincos from smem.
// thc/ths indexed j = layer*9 + qubit*3 + rot.
__device__ void ansatz_pre(cf* s, const float* thc, const float* ths, int layer)
{
    #pragma unroll
    for (int i = 0; i < 3; i++) {
        int j = layer * 9 + i * 3;
        float c, z;
        c = thc[j + 0]; z = ths[j + 0];
        gate1q(s, i, c, -z, 0.f, 0.f, 0.f, 0.f, c, z);          // RZ
        c = thc[j + 1]; z = ths[j + 1];
        gate1q(s, i, c, 0.f, 0.f, -z, 0.f, -z, c, 0.f);         // RX
        c = thc[j + 2]; z = ths[j + 2];
        gate1q(s, i, c, -z, 0.f, 0.f, 0.f, 0.f, c, z);          // RZ
    }
    cnot(s, 0, 1); cnot(s, 1, 2); cnot(s, 2, 0);
}

__device__ void feature(cf* s, float fc[3], float fs_[3])
{
    #pragma unroll
    for (int i = 0; i < 3; i++)
        gate1q(s, i, fc[i], 0.f, -fs_[i], 0.f, fs_[i], 0.f, fc[i], 0.f);  // RY
}

// Trig-poly value f and scaled derivative D = f'(t)*h at t.
__device__ __forceinline__ void poly_fd(float tt, const float* ca,
                                        const float* cb, float& f, float& D)
{
    float c1v, s1v; __sincosf(PI_F * tt, &s1v, &c1v);
    f = fmaf(ca[1], c1v, ca[0]);
    f = fmaf(cb[1], s1v, f);
    float g = cb[1]*c1v - ca[1]*s1v;
    const float twoc = c1v + c1v;
    float ckm = 1.f, ck = c1v, skm = 0.f, sk = s1v;
    #pragma unroll
    for (int k = 2; k <= NHARM; k++) {
        float cn = fmaf(twoc, ck, -ckm);
        float sn = fmaf(twoc, sk, -skm);
        f = fmaf(ca[k], cn, f);
        f = fmaf(cb[k], sn, f);
        g = fmaf((float)k, cb[k]*cn - ca[k]*sn, g);
        ckm = ck; ck = cn; skm = sk; sk = sn;
    }
    D = g * (PI_F / (float)TBL);
}

__global__ void __launch_bounds__(THREADS)
precompute_kernel(const float* __restrict__ theta)
{
    __shared__ float thc[27], ths[27];           // theta sincos (parallel)
    __shared__ float twc[NSAMP], tws[NSAMP];     // DFT twiddles (parallel)
    __shared__ float fsamp[NSAMP];
    __shared__ float ca[NHARM + 1], cb[NHARM + 1];
    __shared__ float fv[TBL + 2], Dv[TBL + 2];   // half-grid endpoints
    const int tid = threadIdx.x;

    // ---- parallel trig precompute (removes MUFU from the serial chains) -----
    if (tid < 27)
        __sincosf(0.5f * theta[tid], &ths[tid], &thc[tid]);
    else if (tid >= 32 && tid < 32 + NSAMP) {
        int j = tid - 32;
        __sincosf(TWO_PI_F * (float)j * (1.0f / 25.0f), &tws[j], &twc[j]);
    }
    __syncthreads();

    // ---- 25 circuit samples: short gate chain + 6 feature sincos ------------
    if (tid < NSAMP) {
        float t = 2.0f * (float)tid / 25.0f;
        float fc[3], fs_[3];
        #pragma unroll
        for (int i = 0; i < 3; i++)
            __sincosf(0.5f * PI_F * t * (float)(i + 1), &fs_[i], &fc[i]);

        cf s[8];
        #pragma unroll
        for (int k = 0; k < 8; k++) { s[k].re = 0.f; s[k].im = 0.f; }
        s[0].re = 1.f;
        ansatz_pre(s, thc, ths, 0);
        feature(s, fc, fs_);
        ansatz_pre(s, thc, ths, 1);
        feature(s, fc, fs_);
        ansatz_pre(s, thc, ths, 2);
        float e = 0.f;
        #pragma unroll
        for (int k = 0; k < 8; k++) {
            float p = s[k].re*s[k].re + s[k].im*s[k].im;
            e += (k < 4) ? p : -p;   // Z on qubit 0
        }
        fsamp[tid] = e;
    }
    __syncthreads();

    // ---- exact real DFT, twiddles from smem (incremental mod-25 index) ------
    if (tid < NSAMP) {
        float sum = 0.f;
        if (tid == 0) {
            for (int m = 0; m < NSAMP; m++) sum += fsamp[m];
            ca[0] = sum * (1.0f / 25.0f);
            cb[0] = 0.f;
        } else if (tid <= NHARM) {
            int r = 0;
            for (int m = 0; m < NSAMP; m++) {
                sum = fmaf(fsamp[m], twc[r], sum);
                r += tid; if (r >= 25) r -= 25;
            }
            ca[tid] = sum * (2.0f / 25.0f);
        } else {
            int k = tid - NHARM, r = 0;
            for (int m = 0; m < NSAMP; m++) {
                sum = fmaf(fsamp[m], tws[r], sum);
                r += k; if (r >= 25) r -= 25;
            }
            cb[k] = sum * (2.0f / 25.0f);
        }
    }
    __syncthreads();

    // ---- half-grid endpoints: fv[k] = f((k-0.5)h), k = 0..257 ----------------
    {
        const float h = 1.0f / (float)TBL;
        float f, D;
        poly_fd(((float)tid - 0.5f) * h, ca, cb, f, D);
        fv[tid] = f; Dv[tid] = D;
        if (tid < 2) {
            int k = TBL + tid;           // 256, 257
            poly_fd(((float)k - 0.5f) * h, ca, cb, f, D);
            fv[k] = f; Dv[k] = D;
        }
    }
    __syncthreads();

    // ---- centered cubic entries e = 0..256 (thread tid, thread 0 also 256) --
    for (int e = tid; e <= TBL; e += THREADS) {
        float f0 = fv[e],  D0 = Dv[e];
        float f1 = fv[e+1], D1 = Dv[e+1];
        float h0 = f0;
        float h1 = D0;
        float h2 = 3.f*(f1 - f0) - 2.f*D0 - D1;
        float h3 = 2.f*(f0 - f1) + D0 + D1;
        // re-expand Hermite (v in [0,1]) in u = v - 0.5
        g_table[e] = make_float4(
            h0 + 0.5f*h1 + 0.25f*h2 + 0.125f*h3,
            h1 + h2 + 0.75f*h3,
            h2 + 1.5f*h3,
            h3);
    }
}

__device__ __forceinline__ float interp(float tt, const float4* tbl)
{
    float y = fmaf(tt, (float)TBL, MAGIC);   // round(tt*TBL) in low mantissa
    int   i = __float_as_int(y) & 0x1FF;     // 0..256 for t in [0,1]
    i = min(i, TBL);
    float r = y - MAGIC;
    float u = fmaf(tt, (float)TBL, -r);      // u in [-0.5, 0.5]
    float4 c = tbl[i];
    return fmaf(fmaf(fmaf(c.w, u, c.z), u, c.y), u, c.x);
}

__global__ void __launch_bounds__(THREADS, 8)
eval_kernel(const float* __restrict__ t, float* __restrict__ out, int n)
{
    __shared__ float4 tin[2 * THREADS];   // 8 KB input staging
    __shared__ float4 tbl[TBL + 1];       // 4.1 KB table

    const int tid = threadIdx.x;
    const int vbase = blockIdx.x * (ELEMS_PER_BLOCK / 4);  // float4 index
    const bool full = (vbase + 2 * THREADS) * 4 <= n;

    // ---- stage inputs FIRST: overlaps the still-running precompute ----------
    if (full) {
        const float4* in4 = reinterpret_cast<const float4*>(t);
        tin[tid]           = __ldg(in4 + vbase + tid);
        tin[tid + THREADS] = __ldg(in4 + vbase + THREADS + tid);
    }

    // ---- wait for precompute (PDL), then grab the table ----------------------
    cudaGridDependencySynchronize();
    tbl[tid] = g_table[tid];
    if (tid == 0) tbl[TBL] = g_table[TBL];
    __syncthreads();

    if (full) {
        float4* out4 = reinterpret_cast<float4*>(out);
        #pragma unroll
        for (int j = 0; j < 2; j++) {
            float4 tv = tin[tid + j * THREADS];
            float4 ov;
            ov.x = interp(tv.x, tbl);
            ov.y = interp(tv.y, tbl);
            ov.z = interp(tv.z, tbl);
            ov.w = interp(tv.w, tbl);
            out4[vbase + j * THREADS + tid] = ov;
        }
    } else {
        for (int i = vbase * 4 + tid; i < n; i += THREADS)
            out[i] = interp(t[i], tbl);
    }
}

extern "C" void kernel_launch(void* const* d_in, const int* in_sizes, int n_in,
                              void* d_out, int out_size)
{
    const float* t;
    const float* theta;
    if (n_in >= 2 && in_sizes[0] == 27 && in_sizes[1] != 27) {
        theta = (const float*)d_in[0];
        t     = (const float*)d_in[1];
    } else {
        t     = (const float*)d_in[0];
        theta = (const float*)d_in[1];
    }
    float* out = (float*)d_out;
    const int n = out_size;

    precompute_kernel<<<1, THREADS>>>(theta);

    const int blocks = (n + ELEMS_PER_BLOCK - 1) / ELEMS_PER_BLOCK;  // 1024

    cudaLaunchConfig_t cfg = {};
    cfg.gridDim  = dim3(blocks, 1, 1);
    cfg.blockDim = dim3(THREADS, 1, 1);
    cfg.dynamicSmemBytes = 0;
    cfg.stream = 0;
    cudaLaunchAttribute attrs[1];
    attrs[0].id = cudaLaunchAttributeProgrammaticStreamSerialization;
    attrs[0].val.programmaticStreamSerializationAllowed = 1;
    cfg.attrs = attrs;
    cfg.numAttrs = 1;

    cudaLaunchKernelEx(&cfg, eval_kernel, t, out, n);
}

// round 10
// speedup vs baseline: 1.1278x; 1.1278x over previous
#include <cuda_runtime.h>
#include <math.h>

// ----------------------------------------------------------------------------
// QuantumBranch, two-kernel split + PDL (round 10).
// expz0(t) = degree-12 trig polynomial in (pi*t), exactly.
//   K1 precompute (1 block, parallel critical path): 25 circuit samples ->
//      exact real DFT -> 1025-node CENTERED LINEAR table (float2 = node value,
//      slope*h; u in [-0.5,0.5]) -> __device__ global.
//   K2 eval (1024 blocks, PDL): NO input staging / no load-use barrier --
//      warps run independently so DRAM streaming and the random smem gather
//      overlap across warps instead of phase-aligning chip-wide (the R8/R9
//      8.9us plateau).  Table gather is LDS.64 (8 B/elem, half of cubic).
// Linear error h^2 f''/8 ~ 1e-5 worst at h=1/1024  << 1e-3 tolerance.
// ----------------------------------------------------------------------------

#define NSAMP 25
#define NHARM 12
#define TBL   1024
#define THREADS 256
#define ELEMS_PER_BLOCK (THREADS * 8)
#define PI_F  3.14159265358979323846f
#define TWO_PI_F 6.28318530717958647692f
#define MAGIC 8388608.0f   // 2^23

__device__ float2 g_table[TBL + 1];

struct cf { float re, im; };

__device__ __forceinline__ void gate1q(cf* s, int wire,
    float u00r, float u00i, float u01r, float u01i,
    float u10r, float u10i, float u11r, float u11i)
{
    const int str = 4 >> wire;
    #pragma unroll
    for (int k = 0; k < 8; k++) {
        if (k & str) continue;
        cf a = s[k], b = s[k + str];
        s[k].re       = u00r*a.re - u00i*a.im + u01r*b.re - u01i*b.im;
        s[k].im       = u00r*a.im + u00i*a.re + u01r*b.im + u01i*b.re;
        s[k + str].re = u10r*a.re - u10i*a.im + u11r*b.re - u11i*b.im;
        s[k + str].im = u10r*a.im + u10i*a.re + u11r*b.im + u11i*b.re;
    }
}

__device__ __forceinline__ void cnot(cf* s, int ctrl, int tgt)
{
    const int sc = 4 >> ctrl, st = 4 >> tgt;
    #pragma unroll
    for (int k = 0; k < 8; k++) {
        if (!(k & sc) || (k & st)) continue;
        cf tmp = s[k]; s[k] = s[k + st]; s[k + st] = tmp;
    }
}

__device__ void ansatz_pre(cf* s, const float* thc, const float* ths, int layer)
{
    #pragma unroll
    for (int i = 0; i < 3; i++) {
        int j = layer * 9 + i * 3;
        float c, z;
        c = thc[j + 0]; z = ths[j + 0];
        gate1q(s, i, c, -z, 0.f, 0.f, 0.f, 0.f, c, z);          // RZ
        c = thc[j + 1]; z = ths[j + 1];
        gate1q(s, i, c, 0.f, 0.f, -z, 0.f, -z, c, 0.f);         // RX
        c = thc[j + 2]; z = ths[j + 2];
        gate1q(s, i, c, -z, 0.f, 0.f, 0.f, 0.f, c, z);          // RZ
    }
    cnot(s, 0, 1); cnot(s, 1, 2); cnot(s, 2, 0);
}

__device__ void feature(cf* s, float fc[3], float fs_[3])
{
    #pragma unroll
    for (int i = 0; i < 3; i++)
        gate1q(s, i, fc[i], 0.f, -fs_[i], 0.f, fs_[i], 0.f, fc[i], 0.f);  // RY
}

// Trig-poly value f and scaled derivative D = f'(t)*h at t.
__device__ __forceinline__ void poly_fd(float tt, const float* ca,
                                        const float* cb, float& f, float& D)
{
    float c1v, s1v; __sincosf(PI_F * tt, &s1v, &c1v);
    f = fmaf(ca[1], c1v, ca[0]);
    f = fmaf(cb[1], s1v, f);
    float g = cb[1]*c1v - ca[1]*s1v;
    const float twoc = c1v + c1v;
    float ckm = 1.f, ck = c1v, skm = 0.f, sk = s1v;
    #pragma unroll
    for (int k = 2; k <= NHARM; k++) {
        float cn = fmaf(twoc, ck, -ckm);
        float sn = fmaf(twoc, sk, -skm);
        f = fmaf(ca[k], cn, f);
        f = fmaf(cb[k], sn, f);
        g = fmaf((float)k, cb[k]*cn - ca[k]*sn, g);
        ckm = ck; ck = cn; skm = sk; sk = sn;
    }
    D = g * (PI_F / (float)TBL);
}

__global__ void __launch_bounds__(THREADS)
precompute_kernel(const float* __restrict__ theta)
{
    __shared__ float thc[27], ths[27];
    __shared__ float twc[NSAMP], tws[NSAMP];
    __shared__ float fsamp[NSAMP];
    __shared__ float ca[NHARM + 1], cb[NHARM + 1];
    const int tid = threadIdx.x;

    // parallel trig precompute
    if (tid < 27)
        __sincosf(0.5f * theta[tid], &ths[tid], &thc[tid]);
    else if (tid >= 32 && tid < 32 + NSAMP) {
        int j = tid - 32;
        __sincosf(TWO_PI_F * (float)j * (1.0f / 25.0f), &tws[j], &twc[j]);
    }
    __syncthreads();

    // 25 circuit samples
    if (tid < NSAMP) {
        float t = 2.0f * (float)tid / 25.0f;
        float fc[3], fs_[3];
        #pragma unroll
        for (int i = 0; i < 3; i++)
            __sincosf(0.5f * PI_F * t * (float)(i + 1), &fs_[i], &fc[i]);

        cf s[8];
        #pragma unroll
        for (int k = 0; k < 8; k++) { s[k].re = 0.f; s[k].im = 0.f; }
        s[0].re = 1.f;
        ansatz_pre(s, thc, ths, 0);
        feature(s, fc, fs_);
        ansatz_pre(s, thc, ths, 1);
        feature(s, fc, fs_);
        ansatz_pre(s, thc, ths, 2);
        float e = 0.f;
        #pragma unroll
        for (int k = 0; k < 8; k++) {
            float p = s[k].re*s[k].re + s[k].im*s[k].im;
            e += (k < 4) ? p : -p;   // Z on qubit 0
        }
        fsamp[tid] = e;
    }
    __syncthreads();

    // exact real DFT, smem twiddles, incremental mod-25 index
    if (tid < NSAMP) {
        float sum = 0.f;
        if (tid == 0) {
            for (int m = 0; m < NSAMP; m++) sum += fsamp[m];
            ca[0] = sum * (1.0f / 25.0f);
            cb[0] = 0.f;
        } else if (tid <= NHARM) {
            int r = 0;
            for (int m = 0; m < NSAMP; m++) {
                sum = fmaf(fsamp[m], twc[r], sum);
                r += tid; if (r >= 25) r -= 25;
            }
            ca[tid] = sum * (2.0f / 25.0f);
        } else {
            int k = tid - NHARM, r = 0;
            for (int m = 0; m < NSAMP; m++) {
                sum = fmaf(fsamp[m], tws[r], sum);
                r += k; if (r >= 25) r -= 25;
            }
            cb[k] = sum * (2.0f / 25.0f);
        }
    }
    __syncthreads();

    // 1025 table nodes: (f(e*h), f'(e*h)*h), 4-5 per thread
    for (int e = tid; e <= TBL; e += THREADS) {
        float f, D;
        poly_fd((float)e * (1.0f / (float)TBL), ca, cb, f, D);
        g_table[e] = make_float2(f, D);
    }
}

__device__ __forceinline__ float interp(float tt, const float2* tbl)
{
    float y = fmaf(tt, (float)TBL, MAGIC);   // round(tt*TBL) in low mantissa
    int   i = __float_as_int(y) & 0x7FF;     // 0..1024 for t in [0,1]
    i = min(i, TBL);
    float r = y - MAGIC;
    float u = fmaf(tt, (float)TBL, -r);      // u in [-0.5, 0.5]
    float2 c = tbl[i];
    return fmaf(u, c.y, c.x);
}

__global__ void __launch_bounds__(THREADS)
eval_kernel(const float* __restrict__ t, float* __restrict__ out, int n)
{
    __shared__ float2 tbl[TBL + 2];   // 8.2 KB

    const int tid = threadIdx.x;
    const int vbase = blockIdx.x * (ELEMS_PER_BLOCK / 4);  // float4 index
    const bool full = (vbase + 2 * THREADS) * 4 <= n;

    // wait for precompute (PDL), copy table (float4 pairs: 2 per thread)
    cudaGridDependencySynchronize();
    {
        float4* dst = reinterpret_cast<float4*>(tbl);
        const float4* src = reinterpret_cast<const float4*>(g_table);
        dst[tid]           = src[tid];
        dst[tid + THREADS] = src[tid + THREADS];
        if (tid == 0) tbl[TBL] = g_table[TBL];
    }
    __syncthreads();

    // no staging, no load-use barrier: warps stream independently
    if (full) {
        const float4* in4 = reinterpret_cast<const float4*>(t);
        float4* out4 = reinterpret_cast<float4*>(out);
        float4 ta = __ldg(in4 + vbase + tid);
        float4 tb = __ldg(in4 + vbase + THREADS + tid);
        float4 oa, ob;
        oa.x = interp(ta.x, tbl);
        oa.y = interp(ta.y, tbl);
        oa.z = interp(ta.z, tbl);
        oa.w = interp(ta.w, tbl);
        out4[vbase + tid] = oa;
        ob.x = interp(tb.x, tbl);
        ob.y = interp(tb.y, tbl);
        ob.z = interp(tb.z, tbl);
        ob.w = interp(tb.w, tbl);
        out4[vbase + THREADS + tid] = ob;
    } else {
        for (int i = vbase * 4 + tid; i < n; i += THREADS)
            out[i] = interp(t[i], tbl);
    }
}

extern "C" void kernel_launch(void* const* d_in, const int* in_sizes, int n_in,
                              void* d_out, int out_size)
{
    const float* t;
    const float* theta;
    if (n_in >= 2 && in_sizes[0] == 27 && in_sizes[1] != 27) {
        theta = (const float*)d_in[0];
        t     = (const float*)d_in[1];
    } else {
        t     = (const float*)d_in[0];
        theta = (const float*)d_in[1];
    }
    float* out = (float*)d_out;
    const int n = out_size;

    precompute_kernel<<<1, THREADS>>>(theta);

    const int blocks = (n + ELEMS_PER_BLOCK - 1) / ELEMS_PER_BLOCK;  // 1024

    cudaLaunchConfig_t cfg = {};
    cfg.gridDim  = dim3(blocks, 1, 1);
    cfg.blockDim = dim3(THREADS, 1, 1);
    cfg.dynamicSmemBytes = 0;
    cfg.stream = 0;
    cudaLaunchAttribute attrs[1];
    attrs[0].id = cudaLaunchAttributeProgrammaticStreamSerialization;
    attrs[0].val.programmaticStreamSerializationAllowed = 1;
    cfg.attrs = attrs;
    cfg.numAttrs = 1;

    cudaLaunchKernelEx(&cfg, eval_kernel, t, out, n);
}